// round 1
// baseline (speedup 1.0000x reference)
#include <cuda_runtime.h>
#include <cstdint>

// Problem constants (fixed by the dataset)
#define NN_MAX 50000
#define IN_CH  256
#define C1     128
#define C2     64

// -------- scratch (no allocations allowed -> __device__ globals) -----------
__device__ int   g_deg [NN_MAX];
__device__ float g_dis [NN_MAX];
__device__ float g_hs1 [NN_MAX * C1];   // (x@W1)*dis
__device__ float g_acc1[NN_MAX * C1];   // scatter accumulator, layer 1
__device__ float g_x2  [NN_MAX * C1];   // relu output of layer 1
__device__ float g_hs2 [NN_MAX * C2];   // (x2@W2)*dis
__device__ float g_acc2[NN_MAX * C2];   // scatter accumulator, layer 2

// ---------------------------------------------------------------------------
__global__ void zero_kernel(int n) {
    int idx = blockIdx.x * blockDim.x + threadIdx.x;
    if (idx < n * C1) g_acc1[idx] = 0.0f;
    if (idx < n * C2) g_acc2[idx] = 0.0f;
    if (idx < n)      g_deg[idx]  = 0;
}

__global__ void deg_kernel(const int* __restrict__ dst, int E) {
    int e = blockIdx.x * blockDim.x + threadIdx.x;
    if (e < E) atomicAdd(&g_deg[dst[e]], 1);
}

__global__ void dis_kernel(int n) {
    int i = blockIdx.x * blockDim.x + threadIdx.x;
    if (i < n) g_dis[i] = rsqrtf((float)g_deg[i] + 1.0f);
}

// ---------------------------------------------------------------------------
// C[m][n] = dis[m] * sum_k A[m][k] * B[k][n]
// BM x BN tile per block, 256 threads, thread tile TM x TN.
template<int BM, int BN, int BK, int TM, int TN>
__global__ __launch_bounds__(256)
void gemm_dis(const float* __restrict__ A, const float* __restrict__ B,
              float* __restrict__ C, int M, int N, int K) {
    __shared__ float As[BK][BM];
    __shared__ float Bs[BK][BN];

    const int tid = threadIdx.x;
    const int tx  = tid % (BN / TN);
    const int ty  = tid / (BN / TN);
    const int block_m = blockIdx.y * BM;
    const int block_n = blockIdx.x * BN;

    float acc[TM][TN];
#pragma unroll
    for (int i = 0; i < TM; i++)
#pragma unroll
        for (int j = 0; j < TN; j++) acc[i][j] = 0.0f;

    for (int k0 = 0; k0 < K; k0 += BK) {
        // Load A tile (BM x BK), store transposed into As[k][m]
#pragma unroll
        for (int i = tid * 4; i < BM * BK; i += 256 * 4) {
            int m  = i / BK;
            int kk = i % BK;
            float4 v = make_float4(0.f, 0.f, 0.f, 0.f);
            int gm = block_m + m;
            if (gm < M)
                v = *(const float4*)&A[(size_t)gm * K + k0 + kk];
            As[kk + 0][m] = v.x;
            As[kk + 1][m] = v.y;
            As[kk + 2][m] = v.z;
            As[kk + 3][m] = v.w;
        }
        // Load B tile (BK x BN)
#pragma unroll
        for (int i = tid * 4; i < BK * BN; i += 256 * 4) {
            int kk = i / BN;
            int nn = i % BN;
            float4 v = *(const float4*)&B[(size_t)(k0 + kk) * N + block_n + nn];
            *(float4*)&Bs[kk][nn] = v;
        }
        __syncthreads();

#pragma unroll
        for (int kk = 0; kk < BK; kk++) {
            float a[TM], b[TN];
#pragma unroll
            for (int i = 0; i < TM; i += 4) {
                float4 v = *(const float4*)&As[kk][ty * TM + i];
                a[i + 0] = v.x; a[i + 1] = v.y; a[i + 2] = v.z; a[i + 3] = v.w;
            }
#pragma unroll
            for (int j = 0; j < TN; j += 4) {
                float4 v = *(const float4*)&Bs[kk][tx * TN + j];
                b[j + 0] = v.x; b[j + 1] = v.y; b[j + 2] = v.z; b[j + 3] = v.w;
            }
#pragma unroll
            for (int i = 0; i < TM; i++)
#pragma unroll
                for (int j = 0; j < TN; j++)
                    acc[i][j] = fmaf(a[i], b[j], acc[i][j]);
        }
        __syncthreads();
    }

    // Epilogue: scale by dis[row]
#pragma unroll
    for (int i = 0; i < TM; i++) {
        int gm = block_m + ty * TM + i;
        if (gm >= M) continue;
        float d = g_dis[gm];
#pragma unroll
        for (int j = 0; j < TN; j += 4) {
            float4 v;
            v.x = acc[i][j + 0] * d;
            v.y = acc[i][j + 1] * d;
            v.z = acc[i][j + 2] * d;
            v.w = acc[i][j + 3] * d;
            *(float4*)&C[(size_t)gm * N + block_n + tx * TN + j] = v;
        }
    }
}

// ---------------------------------------------------------------------------
// Scatter-add: acc[dst] += hs[src].  One warp per edge, 128 channels.
__global__ __launch_bounds__(256)
void scatter128(const int* __restrict__ src, const int* __restrict__ dst, int E) {
    int gtid = blockIdx.x * blockDim.x + threadIdx.x;
    int e    = gtid >> 5;
    int lane = gtid & 31;
    if (e >= E) return;
    int s = src[e];
    int d = dst[e];
    float4 v = *(const float4*)(g_hs1 + (size_t)s * C1 + lane * 4);
    float* a = g_acc1 + (size_t)d * C1 + lane * 4;
    atomicAdd(a + 0, v.x);
    atomicAdd(a + 1, v.y);
    atomicAdd(a + 2, v.z);
    atomicAdd(a + 3, v.w);
}

// Half-warp (16 threads) per edge, 64 channels.
__global__ __launch_bounds__(256)
void scatter64(const int* __restrict__ src, const int* __restrict__ dst, int E) {
    int gtid   = blockIdx.x * blockDim.x + threadIdx.x;
    int e      = gtid >> 4;
    int lane16 = gtid & 15;
    if (e >= E) return;
    int s = src[e];
    int d = dst[e];
    float4 v = *(const float4*)(g_hs2 + (size_t)s * C2 + lane16 * 4);
    float* a = g_acc2 + (size_t)d * C2 + lane16 * 4;
    atomicAdd(a + 0, v.x);
    atomicAdd(a + 1, v.y);
    atomicAdd(a + 2, v.z);
    atomicAdd(a + 3, v.w);
}

// ---------------------------------------------------------------------------
// out = relu(dis[i] * (acc + hs) + b)
__global__ void combine_kernel(const float* __restrict__ acc,
                               const float* __restrict__ hs,
                               const float* __restrict__ bias,
                               float* __restrict__ out, int n, int C) {
    int idx   = blockIdx.x * blockDim.x + threadIdx.x;
    int cvecs = C >> 2;
    int total = n * cvecs;
    if (idx >= total) return;
    int i  = idx / cvecs;
    int c4 = idx % cvecs;
    float4 a  = ((const float4*)acc)[idx];
    float4 h  = ((const float4*)hs)[idx];
    float4 bb = ((const float4*)bias)[c4];
    float  d  = g_dis[i];
    float4 r;
    r.x = fmaxf(fmaf(d, a.x + h.x, bb.x), 0.0f);
    r.y = fmaxf(fmaf(d, a.y + h.y, bb.y), 0.0f);
    r.z = fmaxf(fmaf(d, a.z + h.z, bb.z), 0.0f);
    r.w = fmaxf(fmaf(d, a.w + h.w, bb.w), 0.0f);
    ((float4*)out)[idx] = r;
}

// ---------------------------------------------------------------------------
extern "C" void kernel_launch(void* const* d_in, const int* in_sizes, int n_in,
                              void* d_out, int out_size) {
    const float* x  = (const float*)d_in[0];
    const int*   ei = (const int*)d_in[1];
    const float* W1 = (const float*)d_in[2];
    const float* b1 = (const float*)d_in[3];
    const float* W2 = (const float*)d_in[4];
    const float* b2 = (const float*)d_in[5];
    float* out = (float*)d_out;

    const int E = in_sizes[1] / 2;
    const int N = in_sizes[0] / IN_CH;
    const int* src = ei;
    const int* dst = ei + E;

    float *hs1, *acc1, *x2, *hs2, *acc2;
    cudaGetSymbolAddress((void**)&hs1,  g_hs1);
    cudaGetSymbolAddress((void**)&acc1, g_acc1);
    cudaGetSymbolAddress((void**)&x2,   g_x2);
    cudaGetSymbolAddress((void**)&hs2,  g_hs2);
    cudaGetSymbolAddress((void**)&acc2, g_acc2);

    // 1. zero accumulators + degree
    {
        int total = N * C1;
        zero_kernel<<<(total + 255) / 256, 256>>>(N);
    }
    // 2. degree count
    deg_kernel<<<(E + 255) / 256, 256>>>(dst, E);
    // 3. dis = rsqrt(deg + 1)
    dis_kernel<<<(N + 255) / 256, 256>>>(N);

    // ---- layer 1 ----
    {
        dim3 grid(C1 / 128, (N + 63) / 64);
        gemm_dis<64, 128, 32, 8, 4><<<grid, 256>>>(x, W1, hs1, N, C1, IN_CH);
    }
    scatter128<<<(E * 32 + 255) / 256, 256>>>(src, dst, E);
    {
        int total = N * (C1 / 4);
        combine_kernel<<<(total + 255) / 256, 256>>>(acc1, hs1, b1, x2, N, C1);
    }

    // ---- layer 2 ----
    {
        dim3 grid(C2 / 64, (N + 63) / 64);
        gemm_dis<64, 64, 32, 4, 4><<<grid, 256>>>(x2, W2, hs2, N, C2, C1);
    }
    scatter64<<<(E * 16 + 255) / 256, 256>>>(src, dst, E);
    {
        int total = N * (C2 / 4);
        combine_kernel<<<(total + 255) / 256, 256>>>(acc2, hs2, b2, out, N, C2);
    }
}

// round 2
// speedup vs baseline: 1.5768x; 1.5768x over previous
#include <cuda_runtime.h>
#include <cstdint>

// Problem constants (fixed by the dataset)
#define NN_MAX 50000
#define EDGE_MAX 800000
#define IN_CH  256
#define C1     128
#define C2     64

// -------- scratch (no allocations allowed -> __device__ globals) -----------
__device__ int   g_deg     [NN_MAX];
__device__ int   g_rowstart[NN_MAX];
__device__ int   g_cursor  [NN_MAX];
__device__ int   g_csr     [EDGE_MAX];     // src ids grouped by dst
__device__ float g_dis     [NN_MAX];
__device__ float g_hs1     [NN_MAX * C1];  // (x@W1)*dis
__device__ float g_x2      [NN_MAX * C1];  // relu output of layer 1
__device__ float g_hs2     [NN_MAX * C2];  // (x2@W2)*dis

// ---------------------------------------------------------------------------
__global__ void zero_deg(int n) {
    int i = blockIdx.x * blockDim.x + threadIdx.x;
    if (i < n) g_deg[i] = 0;
}

__global__ void deg_kernel(const int* __restrict__ dst, int E) {
    int e = blockIdx.x * blockDim.x + threadIdx.x;
    if (e < E) atomicAdd(&g_deg[dst[e]], 1);
}

// Single-block scan: exclusive prefix of deg -> rowstart/cursor, plus dis.
__global__ __launch_bounds__(1024)
void scan_kernel(int n) {
    __shared__ int ssum[1024];
    const int t = threadIdx.x;
    const int chunk = (n + 1023) / 1024;
    const int beg = t * chunk;
    const int end = min(beg + chunk, n);

    int s = 0;
    for (int i = beg; i < end; i++) s += g_deg[i];
    ssum[t] = s;
    __syncthreads();
    // Hillis-Steele inclusive scan
    for (int off = 1; off < 1024; off <<= 1) {
        int v = (t >= off) ? ssum[t - off] : 0;
        __syncthreads();
        ssum[t] += v;
        __syncthreads();
    }
    int run = (t == 0) ? 0 : ssum[t - 1];
    for (int i = beg; i < end; i++) {
        int d = g_deg[i];
        g_rowstart[i] = run;
        g_cursor[i]   = run;
        g_dis[i]      = rsqrtf((float)d + 1.0f);
        run += d;
    }
}

__global__ void fill_csr(const int* __restrict__ src, const int* __restrict__ dst, int E) {
    int e = blockIdx.x * blockDim.x + threadIdx.x;
    if (e >= E) return;
    int d = dst[e];
    int p = atomicAdd(&g_cursor[d], 1);
    g_csr[p] = src[e];
}

// ---------------------------------------------------------------------------
// C[m][n] = dis[m] * sum_k A[m][k] * B[k][n]
template<int BM, int BN, int BK, int TM, int TN>
__global__ __launch_bounds__(256)
void gemm_dis(const float* __restrict__ A, const float* __restrict__ B,
              float* __restrict__ C, int M, int N, int K) {
    __shared__ float As[BK][BM];
    __shared__ float Bs[BK][BN];

    const int tid = threadIdx.x;
    const int tx  = tid % (BN / TN);
    const int ty  = tid / (BN / TN);
    const int block_m = blockIdx.y * BM;
    const int block_n = blockIdx.x * BN;

    float acc[TM][TN];
#pragma unroll
    for (int i = 0; i < TM; i++)
#pragma unroll
        for (int j = 0; j < TN; j++) acc[i][j] = 0.0f;

    for (int k0 = 0; k0 < K; k0 += BK) {
#pragma unroll
        for (int i = tid * 4; i < BM * BK; i += 256 * 4) {
            int m  = i / BK;
            int kk = i % BK;
            float4 v = make_float4(0.f, 0.f, 0.f, 0.f);
            int gm = block_m + m;
            if (gm < M)
                v = *(const float4*)&A[(size_t)gm * K + k0 + kk];
            As[kk + 0][m] = v.x;
            As[kk + 1][m] = v.y;
            As[kk + 2][m] = v.z;
            As[kk + 3][m] = v.w;
        }
#pragma unroll
        for (int i = tid * 4; i < BK * BN; i += 256 * 4) {
            int kk = i / BN;
            int nn = i % BN;
            float4 v = *(const float4*)&B[(size_t)(k0 + kk) * N + block_n + nn];
            *(float4*)&Bs[kk][nn] = v;
        }
        __syncthreads();

#pragma unroll
        for (int kk = 0; kk < BK; kk++) {
            float a[TM], b[TN];
#pragma unroll
            for (int i = 0; i < TM; i += 4) {
                float4 v = *(const float4*)&As[kk][ty * TM + i];
                a[i + 0] = v.x; a[i + 1] = v.y; a[i + 2] = v.z; a[i + 3] = v.w;
            }
#pragma unroll
            for (int j = 0; j < TN; j += 4) {
                float4 v = *(const float4*)&Bs[kk][tx * TN + j];
                b[j + 0] = v.x; b[j + 1] = v.y; b[j + 2] = v.z; b[j + 3] = v.w;
            }
#pragma unroll
            for (int i = 0; i < TM; i++)
#pragma unroll
                for (int j = 0; j < TN; j++)
                    acc[i][j] = fmaf(a[i], b[j], acc[i][j]);
        }
        __syncthreads();
    }

#pragma unroll
    for (int i = 0; i < TM; i++) {
        int gm = block_m + ty * TM + i;
        if (gm >= M) continue;
        float d = g_dis[gm];
#pragma unroll
        for (int j = 0; j < TN; j += 4) {
            float4 v;
            v.x = acc[i][j + 0] * d;
            v.y = acc[i][j + 1] * d;
            v.z = acc[i][j + 2] * d;
            v.w = acc[i][j + 3] * d;
            *(float4*)&C[(size_t)gm * N + block_n + tx * TN + j] = v;
        }
    }
}

// ---------------------------------------------------------------------------
// Gather-reduce aggregation, 128 channels: one warp per dst node.
// out[i] = relu(dis[i] * (sum_{e: dst=i} hs[src_e] + hs[i]) + b)
__global__ __launch_bounds__(256)
void agg128(const float* __restrict__ hs, const float* __restrict__ bias,
            float* __restrict__ out, int n) {
    int warp = (blockIdx.x * blockDim.x + threadIdx.x) >> 5;
    int lane = threadIdx.x & 31;
    if (warp >= n) return;
    const int node = warp;

    float4 acc = *(const float4*)&hs[(size_t)node * C1 + lane * 4]; // self-loop term
    int e   = g_rowstart[node];
    int cnt = g_deg[node];

    while (cnt > 0) {
        int take = min(cnt, 32);
        int s = 0;
        if (lane < take) s = g_csr[e + lane];
        int k = 0;
        for (; k + 4 <= take; k += 4) {
            int s0 = __shfl_sync(0xffffffffu, s, k + 0);
            int s1 = __shfl_sync(0xffffffffu, s, k + 1);
            int s2 = __shfl_sync(0xffffffffu, s, k + 2);
            int s3 = __shfl_sync(0xffffffffu, s, k + 3);
            float4 v0 = *(const float4*)&hs[(size_t)s0 * C1 + lane * 4];
            float4 v1 = *(const float4*)&hs[(size_t)s1 * C1 + lane * 4];
            float4 v2 = *(const float4*)&hs[(size_t)s2 * C1 + lane * 4];
            float4 v3 = *(const float4*)&hs[(size_t)s3 * C1 + lane * 4];
            acc.x += (v0.x + v1.x) + (v2.x + v3.x);
            acc.y += (v0.y + v1.y) + (v2.y + v3.y);
            acc.z += (v0.z + v1.z) + (v2.z + v3.z);
            acc.w += (v0.w + v1.w) + (v2.w + v3.w);
        }
        for (; k < take; k++) {
            int sk = __shfl_sync(0xffffffffu, s, k);
            float4 v = *(const float4*)&hs[(size_t)sk * C1 + lane * 4];
            acc.x += v.x; acc.y += v.y; acc.z += v.z; acc.w += v.w;
        }
        e += take; cnt -= take;
    }

    float d   = g_dis[node];
    float4 bb = ((const float4*)bias)[lane];
    float4 r;
    r.x = fmaxf(fmaf(d, acc.x, bb.x), 0.0f);
    r.y = fmaxf(fmaf(d, acc.y, bb.y), 0.0f);
    r.z = fmaxf(fmaf(d, acc.z, bb.z), 0.0f);
    r.w = fmaxf(fmaf(d, acc.w, bb.w), 0.0f);
    *(float4*)&out[(size_t)node * C1 + lane * 4] = r;
}

// 64-channel variant: one warp per node, float2 per lane.
__global__ __launch_bounds__(256)
void agg64(const float* __restrict__ hs, const float* __restrict__ bias,
           float* __restrict__ out, int n) {
    int warp = (blockIdx.x * blockDim.x + threadIdx.x) >> 5;
    int lane = threadIdx.x & 31;
    if (warp >= n) return;
    const int node = warp;

    float2 acc = *(const float2*)&hs[(size_t)node * C2 + lane * 2];
    int e   = g_rowstart[node];
    int cnt = g_deg[node];

    while (cnt > 0) {
        int take = min(cnt, 32);
        int s = 0;
        if (lane < take) s = g_csr[e + lane];
        int k = 0;
        for (; k + 4 <= take; k += 4) {
            int s0 = __shfl_sync(0xffffffffu, s, k + 0);
            int s1 = __shfl_sync(0xffffffffu, s, k + 1);
            int s2 = __shfl_sync(0xffffffffu, s, k + 2);
            int s3 = __shfl_sync(0xffffffffu, s, k + 3);
            float2 v0 = *(const float2*)&hs[(size_t)s0 * C2 + lane * 2];
            float2 v1 = *(const float2*)&hs[(size_t)s1 * C2 + lane * 2];
            float2 v2 = *(const float2*)&hs[(size_t)s2 * C2 + lane * 2];
            float2 v3 = *(const float2*)&hs[(size_t)s3 * C2 + lane * 2];
            acc.x += (v0.x + v1.x) + (v2.x + v3.x);
            acc.y += (v0.y + v1.y) + (v2.y + v3.y);
        }
        for (; k < take; k++) {
            int sk = __shfl_sync(0xffffffffu, s, k);
            float2 v = *(const float2*)&hs[(size_t)sk * C2 + lane * 2];
            acc.x += v.x; acc.y += v.y;
        }
        e += take; cnt -= take;
    }

    float d   = g_dis[node];
    float2 bb = ((const float2*)bias)[lane];
    float2 r;
    r.x = fmaxf(fmaf(d, acc.x, bb.x), 0.0f);
    r.y = fmaxf(fmaf(d, acc.y, bb.y), 0.0f);
    *(float2*)&out[(size_t)node * C2 + lane * 2] = r;
}

// ---------------------------------------------------------------------------
extern "C" void kernel_launch(void* const* d_in, const int* in_sizes, int n_in,
                              void* d_out, int out_size) {
    const float* x  = (const float*)d_in[0];
    const int*   ei = (const int*)d_in[1];
    const float* W1 = (const float*)d_in[2];
    const float* b1 = (const float*)d_in[3];
    const float* W2 = (const float*)d_in[4];
    const float* b2 = (const float*)d_in[5];
    float* out = (float*)d_out;

    const int E = in_sizes[1] / 2;
    const int N = in_sizes[0] / IN_CH;
    const int* src = ei;
    const int* dst = ei + E;

    float *hs1, *x2, *hs2;
    cudaGetSymbolAddress((void**)&hs1, g_hs1);
    cudaGetSymbolAddress((void**)&x2,  g_x2);
    cudaGetSymbolAddress((void**)&hs2, g_hs2);

    // Build degree + dis + CSR (dst-grouped src lists)
    zero_deg<<<(N + 255) / 256, 256>>>(N);
    deg_kernel<<<(E + 255) / 256, 256>>>(dst, E);
    scan_kernel<<<1, 1024>>>(N);
    fill_csr<<<(E + 255) / 256, 256>>>(src, dst, E);

    // ---- layer 1 ----
    {
        dim3 grid(C1 / 128, (N + 63) / 64);
        gemm_dis<64, 128, 32, 8, 4><<<grid, 256>>>(x, W1, hs1, N, C1, IN_CH);
    }
    agg128<<<(N * 32 + 255) / 256, 256>>>(hs1, b1, x2, N);

    // ---- layer 2 ----
    {
        dim3 grid(C2 / 64, (N + 63) / 64);
        gemm_dis<64, 64, 32, 4, 4><<<grid, 256>>>(x2, W2, hs2, N, C2, C1);
    }
    agg64<<<(N * 32 + 255) / 256, 256>>>(hs2, b2, out, N);
}

// round 5
// speedup vs baseline: 2.5666x; 1.6277x over previous
#include <cuda_runtime.h>
#include <cuda_bf16.h>
#include <cstdint>

// Problem constants (fixed by the dataset)
#define NN_MAX   50000
#define EDGE_MAX 800000
#define IN_CH    256
#define C1       128
#define C2       64

// -------- scratch (no allocations allowed -> __device__ globals) -----------
__device__ int   g_deg     [NN_MAX];
__device__ int   g_prefix  [NN_MAX];
__device__ int   g_bsum    [256];
__device__ int   g_rowstart[NN_MAX];
__device__ int   g_cursor  [NN_MAX];
__device__ int   g_csr     [EDGE_MAX];
__device__ float g_dis     [NN_MAX];
__device__ float g_hs1     [NN_MAX * C1];
__device__ float g_x2      [NN_MAX * C1];
__device__ float g_hs2     [NN_MAX * C2];
// Pre-swizzled (SW128) bf16 hi/lo images of W^T, layout [kchunk][n][k64], 128B rows.
__device__ uint4 g_W1hi[4096], g_W1lo[4096];   // 4 chunks x 128n x 128B
__device__ uint4 g_W2hi[1024], g_W2lo[1024];   // 2 chunks x  64n x 128B

#define SW128(o) ((o) ^ (((o) >> 3) & 0x70))

__device__ __forceinline__ uint32_t smem_u32(const void* p) {
    uint32_t a;
    asm("{ .reg .u64 t; cvta.to.shared.u64 t, %1; cvt.u32.u64 %0, t; }" : "=r"(a) : "l"(p));
    return a;
}
__device__ __forceinline__ void ldsm_x4(uint32_t* r, uint32_t addr) {
    asm volatile("ldmatrix.sync.aligned.m8n8.x4.shared.b16 {%0,%1,%2,%3}, [%4];"
                 : "=r"(r[0]), "=r"(r[1]), "=r"(r[2]), "=r"(r[3]) : "r"(addr));
}
__device__ __forceinline__ void mma_bf16(float* d, const uint32_t* a,
                                         uint32_t b0, uint32_t b1) {
    asm volatile(
        "mma.sync.aligned.m16n8k16.row.col.f32.bf16.bf16.f32 "
        "{%0,%1,%2,%3}, {%4,%5,%6,%7}, {%8,%9}, {%0,%1,%2,%3};"
        : "+f"(d[0]), "+f"(d[1]), "+f"(d[2]), "+f"(d[3])
        : "r"(a[0]), "r"(a[1]), "r"(a[2]), "r"(a[3]), "r"(b0), "r"(b1));
}

// ---------------------------------------------------------------------------
__global__ void zero_deg(int n) {
    int i = blockIdx.x * blockDim.x + threadIdx.x;
    if (i < n) g_deg[i] = 0;
}
__global__ void deg_kernel(const int* __restrict__ dst, int E) {
    int e = blockIdx.x * blockDim.x + threadIdx.x;
    if (e < E) atomicAdd(&g_deg[dst[e]], 1);
}
// 3-phase parallel exclusive scan of g_deg -> rowstart/cursor (+dis)
__global__ __launch_bounds__(512) void scanA(int n) {
    __shared__ int s[512];
    int t = threadIdx.x;
    int i = blockIdx.x * 512 + t;
    int v = (i < n) ? g_deg[i] : 0;
    s[t] = v; __syncthreads();
    for (int off = 1; off < 512; off <<= 1) {
        int u = (t >= off) ? s[t - off] : 0;
        __syncthreads(); s[t] += u; __syncthreads();
    }
    if (i < n) g_prefix[i] = s[t] - v;
    if (t == 511) g_bsum[blockIdx.x] = s[511];
}
__global__ __launch_bounds__(256) void scanB(int nb) {
    __shared__ int s[256];
    int t = threadIdx.x;
    int v = (t < nb) ? g_bsum[t] : 0;
    s[t] = v; __syncthreads();
    for (int off = 1; off < 256; off <<= 1) {
        int u = (t >= off) ? s[t - off] : 0;
        __syncthreads(); s[t] += u; __syncthreads();
    }
    if (t < nb) g_bsum[t] = s[t] - v;
}
__global__ void scanC(int n) {
    int i = blockIdx.x * blockDim.x + threadIdx.x;
    if (i >= n) return;
    int base = g_bsum[i >> 9] + g_prefix[i];
    g_rowstart[i] = base;
    g_cursor[i]   = base;
    g_dis[i]      = rsqrtf((float)g_deg[i] + 1.0f);
}
__global__ void fill_csr(const int* __restrict__ src, const int* __restrict__ dst, int E) {
    int e = blockIdx.x * blockDim.x + threadIdx.x;
    if (e >= E) return;
    int d = dst[e];
    int p = atomicAdd(&g_cursor[d], 1);
    g_csr[p] = src[e];
}

// ---------------------------------------------------------------------------
// Build swizzled bf16 hi/lo images of W1^T, W2^T: [chunk][n][k in 64], 128B rows.
__global__ void wprep(const float* __restrict__ W1, const float* __restrict__ W2) {
    int idx = blockIdx.x * blockDim.x + threadIdx.x;
    if (idx < IN_CH * C1) {
        int k = idx / C1, n = idx % C1;
        float v = W1[k * C1 + n];
        __nv_bfloat16 h = __float2bfloat16_rn(v);
        __nv_bfloat16 l = __float2bfloat16_rn(v - __bfloat162float(h));
        int c = k >> 6, kk = k & 63;
        int off = c * 16384 + SW128(n * 128 + kk * 2);
        *(__nv_bfloat16*)((char*)g_W1hi + off) = h;
        *(__nv_bfloat16*)((char*)g_W1lo + off) = l;
    } else if (idx < IN_CH * C1 + C1 * C2) {
        int e = idx - IN_CH * C1;
        int k = e / C2, n = e % C2;
        float v = W2[k * C2 + n];
        __nv_bfloat16 h = __float2bfloat16_rn(v);
        __nv_bfloat16 l = __float2bfloat16_rn(v - __bfloat162float(h));
        int c = k >> 6, kk = k & 63;
        int off = c * 8192 + SW128(n * 128 + kk * 2);
        *(__nv_bfloat16*)((char*)g_W2hi + off) = h;
        *(__nv_bfloat16*)((char*)g_W2lo + off) = l;
    }
}

// ---------------------------------------------------------------------------
// Warp-MMA split-bf16 GEMM: C[m][n] = dis[m] * sum_k A[m][k] * W[k][n]
// 3-term compensation: Ah*Bh + Ah*Bl + Al*Bh (drops only Al*Bl ~ 2^-18).
// CTA tile MTILE x NDIM, k-chunks of 64. Warp tile 32 x 64 (WM x WN warps).
template<int MTILE, int NDIM, int KDIM, int WM, int WN>
__global__ __launch_bounds__(256) void gemm_mma(
    const float* __restrict__ A, const uint4* __restrict__ Bhi,
    const uint4* __restrict__ Blo, float* __restrict__ Cout, int M)
{
    constexpr int SA_HI = 0;
    constexpr int SA_LO = MTILE * 128;
    constexpr int SB_HI = 2 * MTILE * 128;
    constexpr int SB_LO = SB_HI + NDIM * 128;
    constexpr int NCH   = KDIM / 64;
    constexpr int BNV   = NDIM * 8;   // uint4 per B image chunk

    extern __shared__ char smem[];
    const uint32_t sb = smem_u32(smem);
    const int tid  = threadIdx.x;
    const int wid  = tid >> 5, lane = tid & 31;
    const int wm   = wid / WN, wn = wid % WN;
    const int m0   = blockIdx.x * MTILE;

    const int row_l  = lane & 15;          // ldmatrix row within 16
    const int colsel = (lane >> 4) * 8;    // k half select

    float acc[2][NDIM / 8][4];
#pragma unroll
    for (int i = 0; i < 2; i++)
#pragma unroll
        for (int j = 0; j < NDIM / 8; j++)
#pragma unroll
            for (int q = 0; q < 4; q++) acc[i][j][q] = 0.0f;

    for (int c = 0; c < NCH; c++) {
        // ---- stage A chunk: MTILE rows x 64 cols fp32 -> hi/lo bf16, SW128
        for (int i = tid; i < MTILE * 16; i += 256) {
            int m = i >> 4, kk = (i & 15) * 4;
            int gm = m0 + m;
            float4 v = make_float4(0.f, 0.f, 0.f, 0.f);
            if (gm < M) v = *(const float4*)&A[(size_t)gm * KDIM + c * 64 + kk];
            __nv_bfloat16 h0 = __float2bfloat16_rn(v.x), h1 = __float2bfloat16_rn(v.y);
            __nv_bfloat16 h2 = __float2bfloat16_rn(v.z), h3 = __float2bfloat16_rn(v.w);
            __nv_bfloat16 l0 = __float2bfloat16_rn(v.x - __bfloat162float(h0));
            __nv_bfloat16 l1 = __float2bfloat16_rn(v.y - __bfloat162float(h1));
            __nv_bfloat16 l2 = __float2bfloat16_rn(v.z - __bfloat162float(h2));
            __nv_bfloat16 l3 = __float2bfloat16_rn(v.w - __bfloat162float(h3));
            uint32_t hA = ((uint32_t)__bfloat16_as_ushort(h1) << 16) | __bfloat16_as_ushort(h0);
            uint32_t hB = ((uint32_t)__bfloat16_as_ushort(h3) << 16) | __bfloat16_as_ushort(h2);
            uint32_t lA = ((uint32_t)__bfloat16_as_ushort(l1) << 16) | __bfloat16_as_ushort(l0);
            uint32_t lB = ((uint32_t)__bfloat16_as_ushort(l3) << 16) | __bfloat16_as_ushort(l2);
            int off = SW128(m * 128 + kk * 2);
            *(uint2*)(smem + SA_HI + off) = make_uint2(hA, hB);
            *(uint2*)(smem + SA_LO + off) = make_uint2(lA, lB);
        }
        // ---- stage B chunk (pre-swizzled images)
        {
            uint4* bh = (uint4*)(smem + SB_HI);
            uint4* bl = (uint4*)(smem + SB_LO);
            const uint4* gh = Bhi + (size_t)c * BNV;
            const uint4* gl = Blo + (size_t)c * BNV;
            for (int i = tid; i < BNV; i += 256) { bh[i] = gh[i]; bl[i] = gl[i]; }
        }
        __syncthreads();

        // ---- compute 4 k16 steps
#pragma unroll
        for (int k16 = 0; k16 < 4; k16++) {
            const int kb = k16 * 16;
            uint32_t ah[2][4], al[2][4];
#pragma unroll
            for (int im = 0; im < 2; im++) {
                int aoff = SW128((wm * 32 + im * 16 + row_l) * 128 + (kb + colsel) * 2);
                ldsm_x4(ah[im], sb + SA_HI + aoff);
                ldsm_x4(al[im], sb + SA_LO + aoff);
            }
#pragma unroll
            for (int j2 = 0; j2 < NDIM / (WN * 16); j2++) {
                int boff = SW128((wn * 64 + j2 * 16 + row_l) * 128 + (kb + colsel) * 2);
                uint32_t bh[4], bl[4];
                ldsm_x4(bh, sb + SB_HI + boff);
                ldsm_x4(bl, sb + SB_LO + boff);
#pragma unroll
                for (int im = 0; im < 2; im++) {
                    float* d0 = acc[im][2 * j2];
                    float* d1 = acc[im][2 * j2 + 1];
                    mma_bf16(d0, ah[im], bh[0], bh[2]);
                    mma_bf16(d0, ah[im], bl[0], bl[2]);
                    mma_bf16(d0, al[im], bh[0], bh[2]);
                    mma_bf16(d1, ah[im], bh[1], bh[3]);
                    mma_bf16(d1, ah[im], bl[1], bl[3]);
                    mma_bf16(d1, al[im], bh[1], bh[3]);
                }
            }
        }
        __syncthreads();
    }

    // ---- epilogue: scale by dis[row], store
#pragma unroll
    for (int im = 0; im < 2; im++) {
        int row0 = m0 + wm * 32 + im * 16 + (lane >> 2);
        int row1 = row0 + 8;
        float d0 = (row0 < M) ? g_dis[row0] : 0.0f;
        float d1 = (row1 < M) ? g_dis[row1] : 0.0f;
#pragma unroll
        for (int j = 0; j < NDIM / (WN * 8); j++) {
            int col = wn * 64 + j * 8 + (lane & 3) * 2;
            if (row0 < M)
                *(float2*)&Cout[(size_t)row0 * NDIM + col] =
                    make_float2(acc[im][j][0] * d0, acc[im][j][1] * d0);
            if (row1 < M)
                *(float2*)&Cout[(size_t)row1 * NDIM + col] =
                    make_float2(acc[im][j][2] * d1, acc[im][j][3] * d1);
        }
    }
}

// ---------------------------------------------------------------------------
// Gather-reduce aggregation, 128 channels: one warp per dst node.
__global__ __launch_bounds__(256)
void agg128(const float* __restrict__ hs, const float* __restrict__ bias,
            float* __restrict__ out, int n) {
    int warp = (blockIdx.x * blockDim.x + threadIdx.x) >> 5;
    int lane = threadIdx.x & 31;
    if (warp >= n) return;
    const int node = warp;

    float4 acc = *(const float4*)&hs[(size_t)node * C1 + lane * 4];
    int e   = g_rowstart[node];
    int cnt = g_deg[node];

    while (cnt > 0) {
        int take = min(cnt, 32);
        int s = 0;
        if (lane < take) s = g_csr[e + lane];
        int k = 0;
        for (; k + 4 <= take; k += 4) {
            int s0 = __shfl_sync(0xffffffffu, s, k + 0);
            int s1 = __shfl_sync(0xffffffffu, s, k + 1);
            int s2 = __shfl_sync(0xffffffffu, s, k + 2);
            int s3 = __shfl_sync(0xffffffffu, s, k + 3);
            float4 v0 = *(const float4*)&hs[(size_t)s0 * C1 + lane * 4];
            float4 v1 = *(const float4*)&hs[(size_t)s1 * C1 + lane * 4];
            float4 v2 = *(const float4*)&hs[(size_t)s2 * C1 + lane * 4];
            float4 v3 = *(const float4*)&hs[(size_t)s3 * C1 + lane * 4];
            acc.x += (v0.x + v1.x) + (v2.x + v3.x);
            acc.y += (v0.y + v1.y) + (v2.y + v3.y);
            acc.z += (v0.z + v1.z) + (v2.z + v3.z);
            acc.w += (v0.w + v1.w) + (v2.w + v3.w);
        }
        for (; k < take; k++) {
            int sk = __shfl_sync(0xffffffffu, s, k);
            float4 v = *(const float4*)&hs[(size_t)sk * C1 + lane * 4];
            acc.x += v.x; acc.y += v.y; acc.z += v.z; acc.w += v.w;
        }
        e += take; cnt -= take;
    }

    float d   = g_dis[node];
    float4 bb = ((const float4*)bias)[lane];
    float4 r;
    r.x = fmaxf(fmaf(d, acc.x, bb.x), 0.0f);
    r.y = fmaxf(fmaf(d, acc.y, bb.y), 0.0f);
    r.z = fmaxf(fmaf(d, acc.z, bb.z), 0.0f);
    r.w = fmaxf(fmaf(d, acc.w, bb.w), 0.0f);
    *(float4*)&out[(size_t)node * C1 + lane * 4] = r;
}

__global__ __launch_bounds__(256)
void agg64(const float* __restrict__ hs, const float* __restrict__ bias,
           float* __restrict__ out, int n) {
    int warp = (blockIdx.x * blockDim.x + threadIdx.x) >> 5;
    int lane = threadIdx.x & 31;
    if (warp >= n) return;
    const int node = warp;

    float2 acc = *(const float2*)&hs[(size_t)node * C2 + lane * 2];
    int e   = g_rowstart[node];
    int cnt = g_deg[node];

    while (cnt > 0) {
        int take = min(cnt, 32);
        int s = 0;
        if (lane < take) s = g_csr[e + lane];
        int k = 0;
        for (; k + 4 <= take; k += 4) {
            int s0 = __shfl_sync(0xffffffffu, s, k + 0);
            int s1 = __shfl_sync(0xffffffffu, s, k + 1);
            int s2 = __shfl_sync(0xffffffffu, s, k + 2);
            int s3 = __shfl_sync(0xffffffffu, s, k + 3);
            float2 v0 = *(const float2*)&hs[(size_t)s0 * C2 + lane * 2];
            float2 v1 = *(const float2*)&hs[(size_t)s1 * C2 + lane * 2];
            float2 v2 = *(const float2*)&hs[(size_t)s2 * C2 + lane * 2];
            float2 v3 = *(const float2*)&hs[(size_t)s3 * C2 + lane * 2];
            acc.x += (v0.x + v1.x) + (v2.x + v3.x);
            acc.y += (v0.y + v1.y) + (v2.y + v3.y);
        }
        for (; k < take; k++) {
            int sk = __shfl_sync(0xffffffffu, s, k);
            float2 v = *(const float2*)&hs[(size_t)sk * C2 + lane * 2];
            acc.x += v.x; acc.y += v.y;
        }
        e += take; cnt -= take;
    }

    float d   = g_dis[node];
    float2 bb = ((const float2*)bias)[lane];
    float2 r;
    r.x = fmaxf(fmaf(d, acc.x, bb.x), 0.0f);
    r.y = fmaxf(fmaf(d, acc.y, bb.y), 0.0f);
    *(float2*)&out[(size_t)node * C2 + lane * 2] = r;
}

// ---------------------------------------------------------------------------
extern "C" void kernel_launch(void* const* d_in, const int* in_sizes, int n_in,
                              void* d_out, int out_size) {
    const float* x  = (const float*)d_in[0];
    const int*   ei = (const int*)d_in[1];
    const float* W1 = (const float*)d_in[2];
    const float* b1 = (const float*)d_in[3];
    const float* W2 = (const float*)d_in[4];
    const float* b2 = (const float*)d_in[5];
    float* out = (float*)d_out;

    const int E = in_sizes[1] / 2;
    const int N = in_sizes[0] / IN_CH;
    const int* src = ei;
    const int* dst = ei + E;

    float *hs1, *x2, *hs2;
    uint4 *w1h, *w1l, *w2h, *w2l;
    cudaGetSymbolAddress((void**)&hs1, g_hs1);
    cudaGetSymbolAddress((void**)&x2,  g_x2);
    cudaGetSymbolAddress((void**)&hs2, g_hs2);
    cudaGetSymbolAddress((void**)&w1h, g_W1hi);
    cudaGetSymbolAddress((void**)&w1l, g_W1lo);
    cudaGetSymbolAddress((void**)&w2h, g_W2hi);
    cudaGetSymbolAddress((void**)&w2l, g_W2lo);

    constexpr int SMEM1 = 2 * 128 * 128 + 2 * 128 * 128;  // 65536
    constexpr int SMEM2 = 2 * 256 * 128 + 2 * 64 * 128;   // 81920
    cudaFuncSetAttribute(gemm_mma<128, 128, 256, 4, 2>,
                         cudaFuncAttributeMaxDynamicSharedMemorySize, SMEM1);
    cudaFuncSetAttribute(gemm_mma<256, 64, 128, 8, 1>,
                         cudaFuncAttributeMaxDynamicSharedMemorySize, SMEM2);

    // W hi/lo swizzled images (independent of graph build)
    wprep<<<(IN_CH * C1 + C1 * C2 + 255) / 256, 256>>>(W1, W2);

    // degree + dis + CSR
    zero_deg<<<(N + 255) / 256, 256>>>(N);
    deg_kernel<<<(E + 255) / 256, 256>>>(dst, E);
    int nb = (N + 511) / 512;
    scanA<<<nb, 512>>>(N);
    scanB<<<1, 256>>>(nb);
    scanC<<<(N + 255) / 256, 256>>>(N);
    fill_csr<<<(E + 255) / 256, 256>>>(src, dst, E);

    // ---- layer 1 ----
    gemm_mma<128, 128, 256, 4, 2><<<(N + 127) / 128, 256, SMEM1>>>(x, w1h, w1l, hs1, N);
    agg128<<<(N * 32 + 255) / 256, 256>>>(hs1, b1, x2, N);

    // ---- layer 2 ----
    gemm_mma<256, 64, 128, 8, 1><<<(N + 255) / 256, 256, SMEM2>>>(x2, w2h, w2l, hs2, N);
    agg64<<<(N * 32 + 255) / 256, 256>>>(hs2, b2, out, N);
}